// round 3
// baseline (speedup 1.0000x reference)
#include <cuda_runtime.h>
#include <math.h>

// Problem constants (fixed by the dataset)
#define NN 50000
#define NE 800000

// ---------------- device scratch (no allocation allowed) ----------------
__device__ float g_FT[NN * 128];   // per-layer transformed features [N, H*64]
__device__ float g_X[NN * 128];    // layer activations ping buffer  [N, H*64]
__device__ float g_A1[NN * 2];     // dst-side attention logits [N, H]
__device__ float g_A2[NN * 2];     // src-side attention logits [N, H]
__device__ int   g_deg[NN];
__device__ int   g_rowptr[NN + 1];
__device__ int   g_ptmp[NN];
__device__ int   g_csrc[NE];       // CSR (by dst) storing src node ids

// ---------------- CSR build ----------------
__global__ void k_zero_deg() {
    int i = blockIdx.x * blockDim.x + threadIdx.x;
    if (i < NN) g_deg[i] = 0;
}

__global__ void k_count(const int* __restrict__ dst) {
    int e = blockIdx.x * blockDim.x + threadIdx.x;
    if (e < NE) atomicAdd(&g_deg[dst[e]], 1);
}

// single-block exclusive scan over g_deg -> g_rowptr / g_ptmp (warp-shuffle based)
__global__ void k_scan() {
    __shared__ int warp_tot[32];
    __shared__ int warp_pref[32];
    __shared__ int s_total;
    __shared__ int s_carry;
    int tid = threadIdx.x, lane = tid & 31, wid = tid >> 5;
    if (tid == 0) { s_carry = 0; g_rowptr[0] = 0; }
    __syncthreads();
    for (int base = 0; base < NN; base += 1024) {
        int idx = base + tid;
        int v = (idx < NN) ? g_deg[idx] : 0;
        int x = v;
        #pragma unroll
        for (int off = 1; off < 32; off <<= 1) {
            int t = __shfl_up_sync(0xffffffffu, x, off);
            if (lane >= off) x += t;
        }
        if (lane == 31) warp_tot[wid] = x;
        __syncthreads();
        if (wid == 0) {
            int w = warp_tot[lane];
            int y = w;
            #pragma unroll
            for (int off = 1; off < 32; off <<= 1) {
                int t = __shfl_up_sync(0xffffffffu, y, off);
                if (lane >= off) y += t;
            }
            warp_pref[lane] = y - w;   // exclusive prefix of warp totals
            if (lane == 31) s_total = y;
        }
        __syncthreads();
        int incl = x + warp_pref[wid];
        int carry = s_carry;
        if (idx < NN) {
            g_rowptr[idx + 1] = carry + incl;
            g_ptmp[idx]       = carry + incl - v;  // exclusive start offset
        }
        __syncthreads();
        if (tid == 0) s_carry = carry + s_total;
        __syncthreads();
    }
}

__global__ void k_scatter(const int* __restrict__ src, const int* __restrict__ dst) {
    int e = blockIdx.x * blockDim.x + threadIdx.x;
    if (e < NE) {
        int p = atomicAdd(&g_ptmp[dst[e]], 1);
        g_csrc[p] = src[e];
    }
}

// ---------------- GEMM: g_FT = x @ W + b ----------------
// W layout [H, D, 64]; output col c maps to (h = c/64, k = c%64). OUT = H*64.
// 128 threads, 64-row block, 8 x (OUT/16) register tile per thread.
// XSRC == 0: read Xparam (harness input). XSRC == 1: read g_X (device global,
// referenced INSIDE device code only — never passed from host).
template <int D, int OUT, int XSRC>
__global__ void k_gemm(const float* __restrict__ Xparam,
                       const float* __restrict__ W,
                       const float* __restrict__ B) {
    constexpr int TN = OUT / 16;
    __shared__ float Xs[64][33];
    __shared__ float Ws[32][OUT];
    const float* __restrict__ Xp = XSRC ? (const float*)g_X : Xparam;

    int tid = threadIdx.x;
    int tx = tid & 15, ty = tid >> 4;           // 16 x 8 thread grid
    int rowBase = blockIdx.x * 64;

    float acc[8][TN];
    #pragma unroll
    for (int m = 0; m < 8; m++)
        #pragma unroll
        for (int n = 0; n < TN; n++) acc[m][n] = 0.f;

    for (int k0 = 0; k0 < D; k0 += 32) {
        #pragma unroll 4
        for (int i = tid; i < 64 * 32; i += 128) {
            int r = i >> 5, c = i & 31;
            int gr = rowBase + r;
            Xs[r][c] = (gr < NN) ? Xp[gr * D + k0 + c] : 0.f;
        }
        #pragma unroll 4
        for (int i = tid; i < 32 * OUT; i += 128) {
            int r = i / OUT, c = i % OUT;
            Ws[r][c] = W[(c >> 6) * (D * 64) + (k0 + r) * 64 + (c & 63)];
        }
        __syncthreads();
        #pragma unroll
        for (int kk = 0; kk < 32; kk++) {
            float xv[8];
            #pragma unroll
            for (int m = 0; m < 8; m++) xv[m] = Xs[ty * 8 + m][kk];
            #pragma unroll
            for (int n = 0; n < TN; n++) {
                float wv = Ws[kk][n * 16 + tx];
                #pragma unroll
                for (int m = 0; m < 8; m++) acc[m][n] += xv[m] * wv;
            }
        }
        __syncthreads();
    }
    #pragma unroll
    for (int m = 0; m < 8; m++) {
        int gr = rowBase + ty * 8 + m;
        if (gr < NN) {
            #pragma unroll
            for (int n = 0; n < TN; n++) {
                int c = n * 16 + tx;
                g_FT[gr * OUT + c] = acc[m][n] + B[c];
            }
        }
    }
}

// ---------------- attention coefficients: a1/a2 per (node, head) ----------------
template <int H>
__global__ void k_attn(const float* __restrict__ al, const float* __restrict__ bl,
                       const float* __restrict__ ar, const float* __restrict__ br) {
    int gw = (blockIdx.x * blockDim.x + threadIdx.x) >> 5;  // node
    int lane = threadIdx.x & 31;
    if (gw >= NN) return;
    #pragma unroll
    for (int h = 0; h < H; h++) {
        const float* f = g_FT + gw * (H * 64) + h * 64;
        float v0 = f[lane], v1 = f[lane + 32];
        float s1 = v0 * al[h * 64 + lane] + v1 * al[h * 64 + lane + 32];
        float s2 = v0 * ar[h * 64 + lane] + v1 * ar[h * 64 + lane + 32];
        #pragma unroll
        for (int o = 16; o; o >>= 1) {
            s1 += __shfl_xor_sync(0xffffffffu, s1, o);
            s2 += __shfl_xor_sync(0xffffffffu, s2, o);
        }
        if (lane == 0) {
            g_A1[gw * H + h] = s1 + bl[h];
            g_A2[gw * H + h] = s2 + br[h];
        }
    }
}

// ---------------- edge softmax + aggregation + elu ----------------
// one warp per (node, head). Softmax over in-edges of node; normalization is
// post-hoc: out = (sum_e exp(s_e - m) * ft[src_e]) / (sum_e exp(s_e - m)).
// EXT == false: write to g_X (internal global). EXT == true: write to outp
// (harness d_out, legitimately passed as an argument).
template <int H, bool EXT>
__global__ void k_edge(float* __restrict__ outp) {
    int gw = (blockIdx.x * blockDim.x + threadIdx.x) >> 5;
    int lane = threadIdx.x & 31;
    if (gw >= NN * H) return;
    int n = gw / H, h = gw % H;
    int s0 = g_rowptr[n], s1 = g_rowptr[n + 1];
    float* o = (EXT ? outp : (float*)g_X) + n * (H * 64) + h * 64;
    if (s0 == s1) { o[lane] = 0.f; o[lane + 32] = 0.f; return; }

    float a1 = g_A1[n * H + h];

    // pass 1: segment max
    float m = -INFINITY;
    for (int i = s0 + lane; i < s1; i += 32) {
        float s = a1 + g_A2[g_csrc[i] * H + h];
        s = s > 0.f ? s : 0.01f * s;           // leaky_relu(0.01)
        m = fmaxf(m, s);
    }
    #pragma unroll
    for (int o2 = 16; o2; o2 >>= 1) m = fmaxf(m, __shfl_xor_sync(0xffffffffu, m, o2));

    // pass 2: fused exp / denom / weighted gather-accumulate
    float acc0 = 0.f, acc1 = 0.f, den = 0.f;
    for (int base = s0; base < s1; base += 32) {
        int i = base + lane;
        float e = 0.f; int si = 0;
        if (i < s1) {
            si = g_csrc[i];
            float s = a1 + g_A2[si * H + h];
            s = s > 0.f ? s : 0.01f * s;
            e = __expf(s - m);
        }
        den += e;
        int cnt = min(32, s1 - base);
        for (int j = 0; j < cnt; j++) {
            float ej = __shfl_sync(0xffffffffu, e, j);
            int   sj = __shfl_sync(0xffffffffu, si, j);
            const float* f = g_FT + sj * (H * 64) + h * 64;
            acc0 += ej * f[lane];
            acc1 += ej * f[lane + 32];
        }
    }
    #pragma unroll
    for (int o2 = 16; o2; o2 >>= 1) den += __shfl_xor_sync(0xffffffffu, den, o2);

    float r0 = acc0 / den, r1 = acc1 / den;
    r0 = r0 > 0.f ? r0 : (__expf(r0) - 1.f);   // elu
    r1 = r1 > 0.f ? r1 : (__expf(r1) - 1.f);
    o[lane] = r0;
    o[lane + 32] = r1;
}

// ---------------- launch ----------------
extern "C" void kernel_launch(void* const* d_in, const int* in_sizes, int n_in,
                              void* d_out, int out_size) {
    const float* features = (const float*)d_in[0];
    const int*   src = (const int*)d_in[1];
    const int*   dst = (const int*)d_in[2];
    const float* W0  = (const float*)d_in[3];
    const float* b0  = (const float*)d_in[4];
    const float* al0 = (const float*)d_in[5];
    const float* bl0 = (const float*)d_in[6];
    const float* ar0 = (const float*)d_in[7];
    const float* br0 = (const float*)d_in[8];
    const float* W1  = (const float*)d_in[9];
    const float* b1  = (const float*)d_in[10];
    const float* al1 = (const float*)d_in[11];
    const float* bl1 = (const float*)d_in[12];
    const float* ar1 = (const float*)d_in[13];
    const float* br1 = (const float*)d_in[14];
    const float* Wf  = (const float*)d_in[15];
    const float* bf  = (const float*)d_in[16];
    const float* alf = (const float*)d_in[17];
    const float* blf = (const float*)d_in[18];
    const float* arf = (const float*)d_in[19];
    const float* brf = (const float*)d_in[20];
    float* out = (float*)d_out;

    // CSR build (graph shared by all three layers)
    k_zero_deg<<<(NN + 255) / 256, 256>>>();
    k_count<<<(NE + 255) / 256, 256>>>(dst);
    k_scan<<<1, 1024>>>();
    k_scatter<<<(NE + 255) / 256, 256>>>(src, dst);

    const int gemm_blocks = (NN + 63) / 64;
    const int attn_blocks = (NN + 7) / 8;              // warp per node, 8 warps/block
    const int edge_blocks_h2 = (NN * 2 + 7) / 8;       // warp per (node,head)
    const int edge_blocks_h1 = (NN + 7) / 8;

    // ---- layer 0: IN=256 -> [N, 128] ----
    k_gemm<256, 128, 0><<<gemm_blocks, 128>>>(features, W0, b0);
    k_attn<2><<<attn_blocks, 256>>>(al0, bl0, ar0, br0);
    k_edge<2, false><<<edge_blocks_h2, 256>>>(nullptr);

    // ---- layer 1: 128 -> [N, 128] ----
    k_gemm<128, 128, 1><<<gemm_blocks, 128>>>(nullptr, W1, b1);
    k_attn<2><<<attn_blocks, 256>>>(al1, bl1, ar1, br1);
    k_edge<2, false><<<edge_blocks_h2, 256>>>(nullptr);

    // ---- final layer: 128 -> [N, 64] (H=1) ----
    k_gemm<128, 64, 1><<<gemm_blocks, 128>>>(nullptr, Wf, bf);
    k_attn<1><<<attn_blocks, 256>>>(alf, blf, arf, brf);
    k_edge<1, true><<<edge_blocks_h1, 256>>>(out);
}